// round 13
// baseline (speedup 1.0000x reference)
#include <cuda_runtime.h>

// Vanilla tanh RNN: B=512, S=4096, H=40, fp32.
// out = concat( [B*S] per-step fc outputs , [B*H] final hidden )
//
// R13 = R11 with tail reordering + shared x staging.
// One warp per batch, one warp per CTA (512 x 32), per-step BAR.SYNC @nw=1.
// h broadcast via shared double buffer (minimal STS drain set: 32 + 8 pred).
// matvec: a-dot (own row, 20 fma2 on 2 accumulators) issues and completes
// FIRST -> own-row tanh + STS start ~40cy earlier; c-dot (rows 32..39 on
// lanes 0-7 / fc dot on lanes 8-31) trails. x values staged in shared per
// chunk and read by uniform broadcast LDS (no per-step shuffle).
// tanh = single MUFU tanh.approx. Lane 8 stores fc z one step behind.

#define BATCH 512
#define SEQ   4096
#define HID   40
#define KCH   64
#define THREADS 32
#define FULLM 0xffffffffu

typedef unsigned long long u64;

__device__ __forceinline__ u64 pack2(float lo, float hi) {
    u64 r;
    asm("mov.b64 %0, {%1, %2};" : "=l"(r) : "f"(lo), "f"(hi));
    return r;
}
__device__ __forceinline__ void unpack2(u64 v, float& lo, float& hi) {
    asm("mov.b64 {%0, %1}, %2;" : "=f"(lo), "=f"(hi) : "l"(v));
}
__device__ __forceinline__ u64 fma2(u64 a, u64 b, u64 c) {
    u64 d;
    asm("fma.rn.f32x2 %0, %1, %2, %3;" : "=l"(d) : "l"(a), "l"(b), "l"(c));
    return d;
}
__device__ __forceinline__ u64 add2(u64 a, u64 b) {
    u64 d;
    asm("add.rn.f32x2 %0, %1, %2;" : "=l"(d) : "l"(a), "l"(b));
    return d;
}
__device__ __forceinline__ void lds2(u64& a, u64& b, unsigned off) {
    asm volatile("ld.shared.v2.u64 {%0, %1}, [%2];"
                 : "=l"(a), "=l"(b) : "r"(off) : "memory");
}
__device__ __forceinline__ float ldsf(unsigned off) {
    float v;
    asm volatile("ld.shared.f32 %0, [%1];" : "=f"(v) : "r"(off) : "memory");
    return v;
}
__device__ __forceinline__ void sts1(unsigned off, float v) {
    asm volatile("st.shared.f32 [%0], %1;" :: "r"(off), "f"(v) : "memory");
}
__device__ __forceinline__ float tanh_mufu(float z) {
    float r;
    asm("tanh.approx.f32 %0, %1;" : "=f"(r) : "f"(z));
    return r;
}

struct Lane {
    u64 wm[HID / 2], wx[HID / 2];
    float wih_m, cb_m, wih_x, cb_x;
};

// one recurrence step; accumulator inits precomputed above the barrier.
// a-dot completes first (early own-row STS); c-dot trails.
__device__ __forceinline__ float rnn_step(
    unsigned rd, unsigned wr, float ia, float ic, int l,
    const Lane& W, float& hm, float& hxv)
{
    u64 hp[HID / 2];
#pragma unroll
    for (int q = 0; q < HID / 4; q++)
        lds2(hp[2 * q], hp[2 * q + 1], rd + 16u * q);

    // ---- a-dot: own row, 2 accumulators, finishes at ~issue+44 ----
    u64 a0 = pack2(ia, 0.0f);
    u64 a1 = 0ull;
#pragma unroll
    for (int j = 0; j < HID / 2; j += 2) {
        a0 = fma2(W.wm[j + 0], hp[j + 0], a0);
        a1 = fma2(W.wm[j + 1], hp[j + 1], a1);
    }
    u64 am = add2(a0, a1);
    float alo, ahi;
    unpack2(am, alo, ahi);
    hm = tanh_mufu(alo + ahi);
    sts1(wr + 4u * l, hm);             // the 32-store drain set, early

    // ---- c-dot: rows 32..39 (lanes 0-7) / fc (lanes 8-31), trails ----
    u64 c0 = pack2(ic, 0.0f);
    u64 c1 = 0ull;
#pragma unroll
    for (int j = 0; j < HID / 2; j += 2) {
        c0 = fma2(W.wx[j + 0], hp[j + 0], c0);
        c1 = fma2(W.wx[j + 1], hp[j + 1], c1);
    }
    u64 cm = add2(c0, c1);
    float clo, chi;
    unpack2(cm, clo, chi);
    float zc = clo + chi;              // lane>=8: fc_w . h_{t-1} + fc_b
    hxv = tanh_mufu(zc);
    if (l < 8) sts1(wr + 4u * (32 + l), hxv);
    return zc;
}

__global__ void __launch_bounds__(THREADS, 8) rnn_kernel(
    const float* __restrict__ x,       // [B, S]
    const float* __restrict__ hidden,  // [B, H]
    const float* __restrict__ w_ih,    // [H]
    const float* __restrict__ w_hh,    // [H, H]
    const float* __restrict__ b_ih,    // [H]
    const float* __restrict__ b_hh,    // [H]
    const float* __restrict__ fc_w,    // [H]
    const float* __restrict__ fc_b,    // [1]
    float* __restrict__ out)           // [B*S] then [B*H]
{
    __shared__ __align__(16) float buf[2][HID];
    __shared__ __align__(16) float xs[2][KCH];

    const int l  = threadIdx.x;        // one warp per CTA
    const int bg = blockIdx.x;

    Lane W;
#pragma unroll
    for (int j = 0; j < HID / 2; j++)
        W.wm[j] = pack2(w_hh[l * HID + 2 * j], w_hh[l * HID + 2 * j + 1]);

    const float* row2;
    if (l < 8) {
        row2 = &w_hh[(32 + l) * HID];
        W.wih_x = w_ih[32 + l];
        W.cb_x  = b_ih[32 + l] + b_hh[32 + l];
    } else {
        row2 = fc_w;
        W.wih_x = 0.0f;
        W.cb_x  = fc_b[0];
    }
#pragma unroll
    for (int j = 0; j < HID / 2; j++)
        W.wx[j] = pack2(row2[2 * j], row2[2 * j + 1]);

    W.wih_m = w_ih[l];
    W.cb_m  = b_ih[l] + b_hh[l];

    // initial state -> buf0, chunk-0 x -> xs[0]
    float hm = hidden[bg * HID + l];
    float hxv = 0.0f;
    buf[0][l] = hm;
    if (l < 8) {
        hxv = hidden[bg * HID + 32 + l];
        buf[0][32 + l] = hxv;
    }
    xs[0][l]      = x[bg * SEQ + l];
    xs[0][32 + l] = x[bg * SEQ + 32 + l];
    __syncthreads();

    const unsigned off0 = (unsigned)__cvta_generic_to_shared(&buf[0][0]);
    const unsigned off1 = (unsigned)__cvta_generic_to_shared(&buf[1][0]);
    const unsigned xoff0 = (unsigned)__cvta_generic_to_shared(&xs[0][0]);
    const unsigned xoff1 = (unsigned)__cvta_generic_to_shared(&xs[1][0]);

    int p = 0;
    for (int chunk = 0; chunk < SEQ / KCH; chunk++) {
        const int t0  = chunk * KCH;
        const int t0n = (chunk + 1 < SEQ / KCH) ? t0 + KCH : 0;
        // prefetch next chunk's x into registers (stored to xs at chunk end)
        float xna = x[bg * SEQ + t0n + l];
        float xnb = x[bg * SEQ + t0n + 32 + l];
        const unsigned xp = p ? xoff1 : xoff0;

#pragma unroll 4
        for (int k = 0; k < KCH; k += 2) {
            // uniform broadcast loads of this pair's x; latency overlaps the
            // previous step's STS drain / barrier
            float xv0 = ldsf(xp + 4u * k);
            float xv1 = ldsf(xp + 4u * (k + 1));
            float ia0 = fmaf(xv0, W.wih_m, W.cb_m);
            float ic0 = fmaf(xv0, W.wih_x, W.cb_x);
            float ia1 = fmaf(xv1, W.wih_m, W.cb_m);
            float ic1 = fmaf(xv1, W.wih_x, W.cb_x);

            // even step: read buf0, write buf1
            __syncthreads();
            float zc0 = rnn_step(off0, off1, ia0, ic0, l, W, hm, hxv);
            if (l == 8) {
                int ti = t0 + k;
                out[bg * SEQ + (ti ? ti - 1 : 0)] = zc0;
            }
            // odd step: read buf1, write buf0
            __syncthreads();
            float zc1 = rnn_step(off1, off0, ia1, ic1, l, W, hm, hxv);
            if (l == 8) out[bg * SEQ + t0 + k] = zc1;
        }

        // stage next chunk's x (reads of this buffer only resume after the
        // next step barrier -> visible)
        const unsigned xq = p ? xoff0 : xoff1;
        sts1(xq + 4u * l, xna);
        sts1(xq + 4u * (32 + l), xnb);
        p ^= 1;
    }

    // ---- epilogue: out[S-1] = fc . h_{S-1} + fc_b (h is in buf0, SEQ even) ----
    __syncthreads();
    if (l == 8) {
        u64 hp[HID / 2];
#pragma unroll
        for (int q = 0; q < HID / 4; q++)
            lds2(hp[2 * q], hp[2 * q + 1], off0 + 16u * q);
        u64 c0 = pack2(W.cb_x, 0.0f);
        u64 c1 = 0ull;
#pragma unroll
        for (int j = 0; j < HID / 2; j += 2) {
            c0 = fma2(W.wx[j + 0], hp[j + 0], c0);
            c1 = fma2(W.wx[j + 1], hp[j + 1], c1);
        }
        u64 cm = add2(c0, c1);
        float clo, chi;
        unpack2(cm, clo, chi);
        out[bg * SEQ + SEQ - 1] = clo + chi;
    }

    // ---- final hidden ----
    out[BATCH * SEQ + bg * HID + l] = hm;
    if (l < 8) out[BATCH * SEQ + bg * HID + 32 + l] = hxv;
}

extern "C" void kernel_launch(void* const* d_in, const int* in_sizes, int n_in,
                              void* d_out, int out_size) {
    const float* x      = (const float*)d_in[0];
    const float* hidden = (const float*)d_in[1];
    const float* w_ih   = (const float*)d_in[2];
    const float* w_hh   = (const float*)d_in[3];
    const float* b_ih   = (const float*)d_in[4];
    const float* b_hh   = (const float*)d_in[5];
    const float* fc_w   = (const float*)d_in[6];
    const float* fc_b   = (const float*)d_in[7];
    float* out = (float*)d_out;

    rnn_kernel<<<BATCH, THREADS>>>(x, hidden, w_ih, w_hh, b_ih, b_hh,
                                   fc_w, fc_b, out);
}

// round 15
// speedup vs baseline: 1.5114x; 1.5114x over previous
#include <cuda_runtime.h>

// Vanilla tanh RNN: B=512, S=4096, H=40, fp32.
// out = concat( [B*S] per-step fc outputs , [B*H] final hidden )
//
// R14 = R11 with the per-step barrier REMOVED and the loop body made fully
// branch-free. One warp per batch, one warp per CTA (512 x 32).
// Within a single warp the shared-memory ops flow through the in-order LSU:
// an LDS issued after an STS reads the stored data (R5 proved ordering holds
// without a barrier; its slowdown came from per-step divergent branches).
// All conditional stores are SASS-level @p predicated (inline asm), so the
// warp never diverges and no BSSY/BSYNC pairs appear in the hot loop.
// matvec = 40 packed fma.rn.f32x2, interleaved a/c accumulators (a = own
// row, c = rows 32..39 on lanes 0-7 / fc dot on lanes 8-31).
// tanh = single MUFU tanh.approx. Lane 8 stores fc z one step behind.

#define BATCH 512
#define SEQ   4096
#define HID   40
#define KCH   64
#define THREADS 32
#define FULLM 0xffffffffu

typedef unsigned long long u64;

__device__ __forceinline__ u64 pack2(float lo, float hi) {
    u64 r;
    asm("mov.b64 %0, {%1, %2};" : "=l"(r) : "f"(lo), "f"(hi));
    return r;
}
__device__ __forceinline__ void unpack2(u64 v, float& lo, float& hi) {
    asm("mov.b64 {%0, %1}, %2;" : "=f"(lo), "=f"(hi) : "l"(v));
}
__device__ __forceinline__ u64 fma2(u64 a, u64 b, u64 c) {
    u64 d;
    asm("fma.rn.f32x2 %0, %1, %2, %3;" : "=l"(d) : "l"(a), "l"(b), "l"(c));
    return d;
}
__device__ __forceinline__ u64 add2(u64 a, u64 b) {
    u64 d;
    asm("add.rn.f32x2 %0, %1, %2;" : "=l"(d) : "l"(a), "l"(b));
    return d;
}
__device__ __forceinline__ void lds2(u64& a, u64& b, unsigned off) {
    asm volatile("ld.shared.v2.u64 {%0, %1}, [%2];"
                 : "=l"(a), "=l"(b) : "r"(off) : "memory");
}
__device__ __forceinline__ void sts1(unsigned off, float v) {
    asm volatile("st.shared.f32 [%0], %1;" :: "r"(off), "f"(v) : "memory");
}
// predicated shared store: executes only when pred != 0; NO branch emitted
__device__ __forceinline__ void sts1_pred(unsigned off, float v, int pred) {
    asm volatile(
        "{\n\t"
        ".reg .pred p;\n\t"
        "setp.ne.s32 p, %2, 0;\n\t"
        "@p st.shared.f32 [%0], %1;\n\t"
        "}"
        :: "r"(off), "f"(v), "r"(pred) : "memory");
}
// predicated global store: executes only when pred != 0; NO branch emitted
__device__ __forceinline__ void stg_pred(float* ptr, float v, int pred) {
    asm volatile(
        "{\n\t"
        ".reg .pred p;\n\t"
        "setp.ne.s32 p, %2, 0;\n\t"
        "@p st.global.f32 [%0], %1;\n\t"
        "}"
        :: "l"(ptr), "f"(v), "r"(pred) : "memory");
}
__device__ __forceinline__ float tanh_mufu(float z) {
    float r;
    asm("tanh.approx.f32 %0, %1;" : "=f"(r) : "f"(z));
    return r;
}

struct Lane {
    u64 wm[HID / 2], wx[HID / 2];
    float wih_m, cb_m, wih_x, cb_x;
};

// one recurrence step, branch-free; accumulator inits precomputed
__device__ __forceinline__ float rnn_step(
    unsigned rd, unsigned wr, float ia, float ic, int l, int is_low8,
    const Lane& W, float& hm, float& hxv)
{
    u64 hp[HID / 2];
#pragma unroll
    for (int q = 0; q < HID / 4; q++)
        lds2(hp[2 * q], hp[2 * q + 1], rd + 16u * q);

    u64 a0 = pack2(ia, 0.0f);
    u64 c0 = pack2(ic, 0.0f);
#pragma unroll
    for (int j = 0; j < HID / 2; j++) {
        a0 = fma2(W.wm[j], hp[j], a0);
        c0 = fma2(W.wx[j], hp[j], c0);
    }
    float alo, ahi, clo, chi;
    unpack2(a0, alo, ahi);
    unpack2(c0, clo, chi);
    float zm = alo + ahi;
    float zc = clo + chi;              // lane>=8: fc_w . h_{t-1} + fc_b

    hm  = tanh_mufu(zm);
    hxv = tanh_mufu(zc);

    sts1(wr + 4u * l, hm);
    sts1_pred(wr + 4u * (32 + l), hxv, is_low8);
    return zc;
}

__global__ void __launch_bounds__(THREADS, 8) rnn_kernel(
    const float* __restrict__ x,       // [B, S]
    const float* __restrict__ hidden,  // [B, H]
    const float* __restrict__ w_ih,    // [H]
    const float* __restrict__ w_hh,    // [H, H]
    const float* __restrict__ b_ih,    // [H]
    const float* __restrict__ b_hh,    // [H]
    const float* __restrict__ fc_w,    // [H]
    const float* __restrict__ fc_b,    // [1]
    float* __restrict__ out)           // [B*S] then [B*H]
{
    __shared__ __align__(16) float buf[2][HID];

    const int l  = threadIdx.x;        // one warp per CTA
    const int bg = blockIdx.x;
    const int is_low8 = (l < 8) ? 1 : 0;
    const int is_l8   = (l == 8) ? 1 : 0;

    Lane W;
#pragma unroll
    for (int j = 0; j < HID / 2; j++)
        W.wm[j] = pack2(w_hh[l * HID + 2 * j], w_hh[l * HID + 2 * j + 1]);

    const float* row2;
    if (l < 8) {
        row2 = &w_hh[(32 + l) * HID];
        W.wih_x = w_ih[32 + l];
        W.cb_x  = b_ih[32 + l] + b_hh[32 + l];
    } else {
        row2 = fc_w;
        W.wih_x = 0.0f;
        W.cb_x  = fc_b[0];
    }
#pragma unroll
    for (int j = 0; j < HID / 2; j++)
        W.wx[j] = pack2(row2[2 * j], row2[2 * j + 1]);

    W.wih_m = w_ih[l];
    W.cb_m  = b_ih[l] + b_hh[l];

    // initial state -> buf0
    float hm = hidden[bg * HID + l];
    float hxv = 0.0f;
    buf[0][l] = hm;
    if (l < 8) {
        hxv = hidden[bg * HID + 32 + l];
        buf[0][32 + l] = hxv;
    }
    __syncthreads();

    const unsigned off0 = (unsigned)__cvta_generic_to_shared(&buf[0][0]);
    const unsigned off1 = (unsigned)__cvta_generic_to_shared(&buf[1][0]);

    float xa = x[bg * SEQ + l];
    float xb = x[bg * SEQ + 32 + l];

    for (int chunk = 0; chunk < SEQ / KCH; chunk++) {
        const int t0  = chunk * KCH;
        const int t0n = (chunk + 1 < SEQ / KCH) ? t0 + KCH : 0;
        float xan = x[bg * SEQ + t0n + l];
        float xbn = x[bg * SEQ + t0n + 32 + l];

#pragma unroll 4
        for (int k = 0; k < KCH; k += 2) {
            // branchless per-pair prep: x broadcast + accumulator inits
            float xv0 = __shfl_sync(FULLM, (k & 32) ? xb : xa, k & 31);
            float xv1 = __shfl_sync(FULLM, ((k + 1) & 32) ? xb : xa, (k + 1) & 31);
            float ia0 = fmaf(xv0, W.wih_m, W.cb_m);
            float ic0 = fmaf(xv0, W.wih_x, W.cb_x);
            float ia1 = fmaf(xv1, W.wih_m, W.cb_m);
            float ic1 = fmaf(xv1, W.wih_x, W.cb_x);

            // even step: read buf0, write buf1 (no barrier; in-order LSU)
            float zc0 = rnn_step(off0, off1, ia0, ic0, l, is_low8, W, hm, hxv);
            {
                int ti = t0 + k;
                int tp = ti ? ti - 1 : 0;          // SEL, branchless
                stg_pred(out + bg * SEQ + tp, zc0, is_l8);
            }
            // odd step: read buf1, write buf0
            float zc1 = rnn_step(off1, off0, ia1, ic1, l, is_low8, W, hm, hxv);
            stg_pred(out + bg * SEQ + t0 + k, zc1, is_l8);
        }

        xa = xan;
        xb = xbn;
    }

    // ---- epilogue: out[S-1] = fc . h_{S-1} + fc_b (h is in buf0, SEQ even) ----
    __syncthreads();
    if (l == 8) {
        u64 hp[HID / 2];
#pragma unroll
        for (int q = 0; q < HID / 4; q++)
            lds2(hp[2 * q], hp[2 * q + 1], off0 + 16u * q);
        u64 c0 = pack2(W.cb_x, 0.0f);
#pragma unroll
        for (int j = 0; j < HID / 2; j++)
            c0 = fma2(W.wx[j], hp[j], c0);
        float clo, chi;
        unpack2(c0, clo, chi);
        out[bg * SEQ + SEQ - 1] = clo + chi;
    }

    // ---- final hidden ----
    out[BATCH * SEQ + bg * HID + l] = hm;
    if (l < 8) out[BATCH * SEQ + bg * HID + 32 + l] = hxv;
}

extern "C" void kernel_launch(void* const* d_in, const int* in_sizes, int n_in,
                              void* d_out, int out_size) {
    const float* x      = (const float*)d_in[0];
    const float* hidden = (const float*)d_in[1];
    const float* w_ih   = (const float*)d_in[2];
    const float* w_hh   = (const float*)d_in[3];
    const float* b_ih   = (const float*)d_in[4];
    const float* b_hh   = (const float*)d_in[5];
    const float* fc_w   = (const float*)d_in[6];
    const float* fc_b   = (const float*)d_in[7];
    float* out = (float*)d_out;

    rnn_kernel<<<BATCH, THREADS>>>(x, hidden, w_ih, w_hh, b_ih, b_hh,
                                   fc_w, fc_b, out);
}